// round 15
// baseline (speedup 1.0000x reference)
#include <cuda_runtime.h>
#include <math_constants.h>

#define GS 29
#define GS2 841
#define NP 24389
#define DW 15
#define PP 225
#define PK 675
#define VV 64
#define CC 8
#define NROWS 841
#define NSAMP (29*PP)
#define YSTRIDE (29*225)
#define ZSTRIDE (GS2*225)
#define CTC 20

// ---------------- device scratch ----------------
__device__ float g_f00 [VV*VV*VV*CC];
__device__ float g_f50x[VV*VV*VV*CC];
__device__ float g_f50y[VV*VV*VV*CC];
__device__ float g_pdd[3*(size_t)NP*PP];
__device__ float g_b1 [3*(size_t)NP*PP];
__device__ float g_b2 [3*(size_t)NP*PP];

__device__ __forceinline__ float A29(int i) { return (2.f*i + 1.f)/29.f - 1.f; }
__device__ __forceinline__ float to_pix(float t) { return 0.5f*((t + 1.f)*64.f - 1.f); }
__device__ __forceinline__ float SD(int t)  { return 0.4f*((2.f*t + 1.f)/15.f - 1.f); }

#define W5_0 (1.f/9.f)
#define W5_1 (2.f/9.f)
#define W5_2 (3.f/9.f)

// ---------------- K1: channels-last transpose ----------------
__global__ void transpose_kernel(const float* __restrict__ f00,
                                 const float* __restrict__ f50) {
    int idx = blockIdx.x * blockDim.x + threadIdx.x;
    if (idx >= VV*VV*VV) return;
    int x = idx & 63, y = (idx >> 6) & 63, z = idx >> 12;
    int yf = ((z*VV + x)*VV + y) * CC;
    int xf = idx * CC;
#pragma unroll
    for (int c = 0; c < CC; c++) {
        float v0 = f00[((c*VV + z)*VV + y)*VV + x];
        float v5 = f50[((c*VV + z)*VV + y)*VV + x];
        g_f00 [xf + c] = v0;
        g_f50x[xf + c] = v5;
        g_f50y[yf + c] = v5;
    }
}

// clamped trilerp of 8 channels, x-fast channels-last, pixel coords
__device__ __forceinline__ void trilerp8(const float* __restrict__ vol,
                                         float u, float v, float w,
                                         float* out8) {
    float uf = floorf(u), vf = floorf(v), wf = floorf(w);
    float fu = u - uf, fv = v - vf, fw = w - wf;
    int u0 = (int)uf, v0 = (int)vf, w0 = (int)wf;
    int uc[2] = { min(max(u0,0),63), min(max(u0+1,0),63) };
    int vc[2] = { min(max(v0,0),63), min(max(v0+1,0),63) };
    int wc[2] = { min(max(w0,0),63), min(max(w0+1,0),63) };
    float wu[2] = {1.f-fu, fu}, wv[2] = {1.f-fv, fv}, ww[2] = {1.f-fw, fw};
#pragma unroll
    for (int c = 0; c < 8; c++) out8[c] = 0.f;
#pragma unroll
    for (int a = 0; a < 2; a++)
#pragma unroll
      for (int b = 0; b < 2; b++) {
        int base = (wc[a]*64 + vc[b]) * 64;
        float wab = ww[a]*wv[b];
#pragma unroll
        for (int d = 0; d < 2; d++) {
            const float4* p = (const float4*)(vol + (size_t)(base + uc[d]) * 8);
            float wt = wab * wu[d];
            float4 x0 = p[0], x1 = p[1];
            out8[0]+=wt*x0.x; out8[1]+=wt*x0.y; out8[2]+=wt*x0.z; out8[3]+=wt*x0.w;
            out8[4]+=wt*x1.x; out8[5]+=wt*x1.y; out8[6]+=wt*x1.z; out8[7]+=wt*x1.w;
        }
      }
}

__device__ __forceinline__ float4 min4(float4 a, float4 b) {
    return make_float4(fminf(a.x,b.x), fminf(a.y,b.y), fminf(a.z,b.z), fminf(a.w,b.w));
}

// ---------------- separable pooling (used inside pdd only) ----------------
#define POOL_BUF_FLOATS ((225+255+289)*CTC)
#define SMEM_POOLBIG (POOL_BUF_FLOATS*4)

__device__ __forceinline__ void pool_sep_min(float* colT, float* R, float* M, int t) {
    if (t < 255) {
        int r = t / 17, j = t - r*17;
        int cb0 = min(max(j-2, 0), 14), cb1 = min(max(j-1, 0), 14), cb2 = min(j, 14);
        int q0 = (r*15+cb0)*CTC, q1 = (r*15+cb1)*CTC, q2 = (r*15+cb2)*CTC;
        float* ro = R + t*CTC;
#pragma unroll
        for (int y4 = 0; y4 < 4; y4++) {
            int o = y4*4;
            *(float4*)(ro+o) = min4(min4(*(float4*)(colT+q0+o), *(float4*)(colT+q1+o)),
                                    *(float4*)(colT+q2+o));
        }
    }
    __syncthreads();
    if (t < 289) {
        int i = t / 17, j = t - i*17;
        int ra0 = (min(max(i-2,0),14)*17 + j)*CTC;
        int ra1 = (min(max(i-1,0),14)*17 + j)*CTC;
        int ra2 = (min(i,14)*17 + j)*CTC;
        float* mo = M + t*CTC;
#pragma unroll
        for (int y4 = 0; y4 < 4; y4++) {
            int o = y4*4;
            *(float4*)(mo+o) = min4(min4(*(float4*)(R+ra0+o), *(float4*)(R+ra1+o)),
                                    *(float4*)(R+ra2+o));
        }
    }
    __syncthreads();
    if (t < 255) {
        int x = t / 15, y = t - x*15;
        int m0 = (x*17+y)*CTC;
        float* ro = R + t*CTC;
#pragma unroll
        for (int y4 = 0; y4 < 4; y4++) {
            int o = y4*4;
            float4 a = *(float4*)(M+m0+o), b = *(float4*)(M+m0+CTC+o), c = *(float4*)(M+m0+2*CTC+o);
            *(float4*)(ro+o) = make_float4(a.x+b.x+c.x, a.y+b.y+c.y, a.z+b.z+c.z, a.w+b.w+c.w);
        }
    }
    __syncthreads();
}

// ---------------- K2: pdd + fused pool1, separable v-then-u interpolation (round-12) ----------------
#define SLAB_F4 (64*27)
#define VS_F4   1024
#define SMEM_PDD_RAW ((2*SLAB_F4 + 2*VS_F4)*16 + (232+15+29)*4)
#define SMEM_PDD ((SMEM_PDD_RAW > SMEM_POOLBIG) ? SMEM_PDD_RAW : SMEM_POOLBIG)
#define PDD_THREADS 512
#define CPT 13

__global__ void __launch_bounds__(PDD_THREADS, 2)
pdd_slab_kernel(const float* __restrict__ alpha) {
    extern __shared__ char smraw[];
    float4* sLo  = (float4*)smraw;
    float4* sHi  = sLo + SLAB_F4;
    float4* VSa  = sHi + SLAB_F4;
    float4* VSb  = VSa + VS_F4;
    float*  fixf = (float*)(VSb + VS_F4);
    float*  sdisp = fixf + 232;
    float*  a29s  = sdisp + 15;
    float*  colT = (float*)smraw;
    float*  Rbuf = colT + 225*CTC;
    float*  Mbuf = Rbuf + 255*CTC;

    const int r   = blockIdx.x;
    const int k   = blockIdx.y;
    const int tid = threadIdx.x;

    if (tid < 29) a29s[tid] = A29(tid);
    if (tid >= 32 && tid < 47) sdisp[tid-32] = SD(tid-32);

    const int i1 = r / 29, i2 = r - (r/29)*29;
    float aV, cW;
    if (k == 0)      { aV = A29(i2); cW = to_pix(A29(i1)); }
    else             { aV = A29(i1); cW = to_pix(A29(i2)); }
    const float sd0  = SD(0);
    const float vmin = 0.5f*((aV + sd0 + 1.f)*64.f - 1.f);
    const int vbase  = (int)floorf(vmin);
    const float wfl = floorf(cW);
    const float fw  = cW - wfl;
    const int w0 = min(max((int)wfl,   0), 63);
    const int w1 = min(max((int)wfl+1, 0), 63);
    const float vbias = fmaf(aV, 32.f, 31.5f);

    // ---- slab fill (pre-interp fixed axis) ----
    if (k == 0) {
        for (int pos = tid; pos < 64*26; pos += PDD_THREADS) {
            int u = pos & 63, vi = pos >> 6;
            int y = min(max(vbase + vi, 0), 63);
            const float4* p0 = (const float4*)&g_f50x[(size_t)((w0*64 + y)*64 + u)*8];
            const float4* p1 = (const float4*)&g_f50x[(size_t)((w1*64 + y)*64 + u)*8];
            float4 a0=p0[0], b0=p0[1], a1=p1[0], b1=p1[1];
            float4 lo, hi;
            lo.x=a0.x+fw*(a1.x-a0.x); lo.y=a0.y+fw*(a1.y-a0.y); lo.z=a0.z+fw*(a1.z-a0.z); lo.w=a0.w+fw*(a1.w-a0.w);
            hi.x=b0.x+fw*(b1.x-b0.x); hi.y=b0.y+fw*(b1.y-b0.y); hi.z=b0.z+fw*(b1.z-b0.z); hi.w=b0.w+fw*(b1.w-b0.w);
            sLo[u*27+vi]=lo; sHi[u*27+vi]=hi;
        }
    } else if (k == 1) {
        for (int pos = tid; pos < 64*26; pos += PDD_THREADS) {
            int u = pos & 63, vi = pos >> 6;
            int z = min(max(vbase + vi, 0), 63);
            const float4* p0 = (const float4*)&g_f50x[(size_t)((z*64 + w0)*64 + u)*8];
            const float4* p1 = (const float4*)&g_f50x[(size_t)((z*64 + w1)*64 + u)*8];
            float4 a0=p0[0], b0=p0[1], a1=p1[0], b1=p1[1];
            float4 lo, hi;
            lo.x=a0.x+fw*(a1.x-a0.x); lo.y=a0.y+fw*(a1.y-a0.y); lo.z=a0.z+fw*(a1.z-a0.z); lo.w=a0.w+fw*(a1.w-a0.w);
            hi.x=b0.x+fw*(b1.x-b0.x); hi.y=b0.y+fw*(b1.y-b0.y); hi.z=b0.z+fw*(b1.z-b0.z); hi.w=b0.w+fw*(b1.w-b0.w);
            sLo[u*27+vi]=lo; sHi[u*27+vi]=hi;
        }
    } else {
        for (int pos = tid; pos < 64*26; pos += PDD_THREADS) {
            int vi = pos % 26, u = pos / 26;
            int y = min(max(vbase + vi, 0), 63);
            const float4* p0 = (const float4*)&g_f50y[(size_t)((u*64 + w0)*64 + y)*8];
            const float4* p1 = (const float4*)&g_f50y[(size_t)((u*64 + w1)*64 + y)*8];
            float4 a0=p0[0], b0=p0[1], a1=p1[0], b1=p1[1];
            float4 lo, hi;
            lo.x=a0.x+fw*(a1.x-a0.x); lo.y=a0.y+fw*(a1.y-a0.y); lo.z=a0.z+fw*(a1.z-a0.z); lo.w=a0.w+fw*(a1.w-a0.w);
            hi.x=b0.x+fw*(b1.x-b0.x); hi.y=b0.y+fw*(b1.y-b0.y); hi.z=b0.z+fw*(b1.z-b0.z); hi.w=b0.w+fw*(b1.w-b0.w);
            sLo[u*27+vi]=lo; sHi[u*27+vi]=hi;
        }
    }

    if (tid < 29) {
        float px, py, pz;
        if (k < 2) { px = to_pix(A29(tid)); py = to_pix(A29(i2)); pz = to_pix(A29(i1)); }
        else       { px = to_pix(A29(i2)); py = to_pix(A29(i1)); pz = to_pix(A29(tid)); }
        trilerp8(g_f00, px, py, pz, &fixf[tid*8]);
    }
    __syncthreads();

    // ---- stage B: v-interp 15 distinct v values ----
    for (int t = tid; t < 15*64; t += PDD_THREADS) {
        int u, vi;
        if (k == 2) { u = t / 15; vi = t - u*15; }
        else        { vi = t >> 6; u = t & 63; }
        float v = fmaf(SD(vi), 32.f, vbias);
        float vf = floorf(v);
        float fv = v - vf;
        int iv = (int)vf - vbase;
        int v0 = min(max(iv,   0), 25);
        int v1 = min(max(iv+1, 0), 25);
        float4 l0 = sLo[u*27+v0], l1 = sLo[u*27+v1];
        float4 h0 = sHi[u*27+v0], h1 = sHi[u*27+v1];
        float4 lo, hi;
        lo.x=l0.x+fv*(l1.x-l0.x); lo.y=l0.y+fv*(l1.y-l0.y); lo.z=l0.z+fv*(l1.z-l0.z); lo.w=l0.w+fv*(l1.w-l0.w);
        hi.x=h0.x+fv*(h1.x-h0.x); hi.y=h0.y+fv*(h1.y-h0.y); hi.z=h0.z+fv*(h1.z-h0.z); hi.w=h0.w+fv*(h1.w-h0.w);
        int idx = (k == 2) ? (u*16 + vi) : (vi*64 + u);
        VSa[idx] = lo; VSb[idx] = hi;
    }
    __syncthreads();

    // ---- sample loop: 1-D u-lerp of VS ----
    const float a0c = alpha[0], a1c = alpha[1];
    float creg[CPT];
#pragma unroll
    for (int i = 0; i < CPT; i++) {
        int s = tid + i*PDD_THREADS;
        if (s < NSAMP) {
            int na = s / 225;
            int p  = s - na*225;
            int pi = p / 15, pj = p - pi*15;
            int ui = (k == 2) ? pi : pj;
            int vi = (k == 2) ? pj : pi;
            float u = fmaf(a29s[na] + sdisp[ui], 32.f, 31.5f);
            float uf = floorf(u);
            float fu = u - uf;
            int iu = (int)uf;
            int u0 = min(max(iu,   0), 63);
            int u1 = min(max(iu+1, 0), 63);
            int b0 = (k == 2) ? (u0*16 + vi) : (vi*64 + u0);
            int b1 = (k == 2) ? (u1*16 + vi) : (vi*64 + u1);
            float4 a0 = VSa[b0], a1 = VSa[b1];
            float4 h0 = VSb[b0], h1 = VSb[b1];
            const float* fx8 = &fixf[na*8];
            float d, ssd = 0.f;
            d = fx8[0] - (a0.x + fu*(a1.x-a0.x)); ssd += d*d;
            d = fx8[1] - (a0.y + fu*(a1.y-a0.y)); ssd += d*d;
            d = fx8[2] - (a0.z + fu*(a1.z-a0.z)); ssd += d*d;
            d = fx8[3] - (a0.w + fu*(a1.w-a0.w)); ssd += d*d;
            d = fx8[4] - (h0.x + fu*(h1.x-h0.x)); ssd += d*d;
            d = fx8[5] - (h0.y + fu*(h1.y-h0.y)); ssd += d*d;
            d = fx8[6] - (h0.z + fu*(h1.z-h0.z)); ssd += d*d;
            d = fx8[7] - (h0.w + fu*(h1.w-h0.w)); ssd += d*d;
            float cval = a1c + a0c*ssd;
            creg[i] = cval;
            int n = (k < 2) ? (r*29 + na) : (na*841 + r);
            g_pdd[((size_t)k*NP + n)*225 + p] = cval;
        }
    }
    __syncthreads();

    const size_t obase = (size_t)k*NP*225 + ((k < 2) ? (size_t)r*29*225 : (size_t)r*225);
    const size_t nstep = (k < 2) ? (size_t)225 : (size_t)841*225;

#pragma unroll
    for (int cidx = 0; cidx < 2; cidx++) {
        const int na0 = cidx*16;
        const int nv  = cidx ? 13 : 16;
#pragma unroll
        for (int i = 0; i < CPT; i++) {
            int s = tid + i*PDD_THREADS;
            if (s < NSAMP) {
                int na = s / 225;
                int p  = s - na*225;
                int d = na - na0;
                if ((unsigned)d < (unsigned)nv) colT[p*CTC + d] = creg[i];
            }
        }
        __syncthreads();
        pool_sep_min(colT, Rbuf, Mbuf, tid);
        if (tid < 225) {
            int s0 = tid*CTC;
#pragma unroll
            for (int y4 = 0; y4 < 4; y4++) {
                int o = y4*4;
                float4 v0 = *(float4*)(Rbuf+s0+o);
                float4 v1 = *(float4*)(Rbuf+s0+15*CTC+o);
                float4 v2 = *(float4*)(Rbuf+s0+30*CTC+o);
                float rr[4] = {(v0.x+v1.x+v2.x)*(1.f/9.f), (v0.y+v1.y+v2.y)*(1.f/9.f),
                               (v0.z+v1.z+v2.z)*(1.f/9.f), (v0.w+v1.w+v2.w)*(1.f/9.f)};
#pragma unroll
                for (int l = 0; l < 4; l++) {
                    int d = y4*4 + l;
                    if (d < nv)
                        g_b1[obase + (size_t)(na0+d)*nstep + tid] = rr[l];
                }
            }
        }
        __syncthreads();
    }
}

// ---------------- K3: smooth_y register kernel ----------------
__global__ void smooth_y_kernel(const float* __restrict__ in, float* __restrict__ out) {
    int b = blockIdx.x, t = threadIdx.x;
    if (t >= 225) return;
    int k = b / NROWS, rc = b - k*NROWS;
    int iz = rc / 29, ix = rc - iz*29;
    size_t base = ((size_t)k*NP + (size_t)iz*GS2 + ix) * 225;
    float r[29];
    const float* g = in + base + t;
#pragma unroll
    for (int y = 0; y < 29; y++) r[y] = g[(size_t)y*YSTRIDE];
    float* go = out + base + t;
#pragma unroll
    for (int y = 0; y < 29; y++) {
        int y0 = y-2 < 0 ? 0 : y-2;
        int y1 = y-1 < 0 ? 0 : y-1;
        int y3 = y+1 > 28 ? 28 : y+1;
        int y4 = y+2 > 28 ? 28 : y+2;
        go[(size_t)y*YSTRIDE] = W5_0*(r[y0]+r[y4]) + W5_1*(r[y1]+r[y3]) + W5_2*r[y];
    }
}

// ---------------- K: smooth_z register kernel (used twice) ----------------
__global__ void smooth_z_kernel(const float* __restrict__ in, float* __restrict__ out) {
    int b = blockIdx.x, t = threadIdx.x;
    if (t >= 225) return;
    int k = b / NROWS, rc = b - k*NROWS;
    int iy = rc / 29, ix = rc - iy*29;
    size_t base = ((size_t)k*NP + (size_t)iy*GS + ix) * 225;
    float r[29];
    const float* g = in + base + t;
#pragma unroll
    for (int z = 0; z < 29; z++) r[z] = g[(size_t)z*ZSTRIDE];
    float* go = out + base + t;
#pragma unroll
    for (int z = 0; z < 29; z++) {
        int z0 = z-2 < 0 ? 0 : z-2;
        int z1 = z-1 < 0 ? 0 : z-1;
        int z3 = z+1 > 28 ? 28 : z+1;
        int z4 = z+2 > 28 ? 28 : z+2;
        go[(size_t)z*ZSTRIDE] = W5_0*(r[z0]+r[z4]) + W5_1*(r[z1]+r[z3]) + W5_2*r[z];
    }
}

// ---------------- round-6 9-tap pool chunk (measured fastest) ----------------
#define SMEM_POOL ((225*CTC + 289*CTC)*4)

__device__ __forceinline__ void pool_chunk(float* colT, float* MT, int t) {
    if (t < 289) {
        int i = t / 17, j = t - i*17;
        int ra0 = min(max(i-2, 0), 14)*15, ra1 = min(max(i-1, 0), 14)*15, ra2 = min(i, 14)*15;
        int cb0 = min(max(j-2, 0), 14),    cb1 = min(max(j-1, 0), 14),    cb2 = min(j, 14);
        int p0 = (ra0+cb0)*CTC, p1 = (ra0+cb1)*CTC, p2 = (ra0+cb2)*CTC;
        int p3 = (ra1+cb0)*CTC, p4 = (ra1+cb1)*CTC, p5 = (ra1+cb2)*CTC;
        int p6 = (ra2+cb0)*CTC, p7 = (ra2+cb1)*CTC, p8 = (ra2+cb2)*CTC;
        float* mo = MT + t*CTC;
#pragma unroll
        for (int y4 = 0; y4 < 4; y4++) {
            int o = y4*4;
            float4 m = min4(*(float4*)(colT+p0+o), *(float4*)(colT+p1+o));
            m = min4(m, *(float4*)(colT+p2+o));
            m = min4(m, min4(*(float4*)(colT+p3+o), *(float4*)(colT+p4+o)));
            m = min4(m, *(float4*)(colT+p5+o));
            m = min4(m, min4(*(float4*)(colT+p6+o), *(float4*)(colT+p7+o)));
            m = min4(m, *(float4*)(colT+p8+o));
            *(float4*)(mo + o) = m;
        }
    }
    __syncthreads();
    if (t < 225) {
        int i = t / 15, j = t - i*15;
        int b0 = (i*17 + j)*CTC;
        float* co = colT + t*CTC;
#pragma unroll
        for (int y4 = 0; y4 < 4; y4++) {
            int o = y4*4;
            float4 s0 = *(float4*)(MT+b0+o);
            float4 s1 = *(float4*)(MT+b0+CTC+o);
            float4 s2 = *(float4*)(MT+b0+2*CTC+o);
            float4 s3 = *(float4*)(MT+b0+17*CTC+o);
            float4 s4 = *(float4*)(MT+b0+18*CTC+o);
            float4 s5 = *(float4*)(MT+b0+19*CTC+o);
            float4 s6 = *(float4*)(MT+b0+34*CTC+o);
            float4 s7 = *(float4*)(MT+b0+35*CTC+o);
            float4 s8 = *(float4*)(MT+b0+36*CTC+o);
            float4 r;
            r.x = (s0.x+s1.x+s2.x+s3.x+s4.x+s5.x+s6.x+s7.x+s8.x)*(1.f/9.f);
            r.y = (s0.y+s1.y+s2.y+s3.y+s4.y+s5.y+s6.y+s7.y+s8.y)*(1.f/9.f);
            r.z = (s0.z+s1.z+s2.z+s3.z+s4.z+s5.z+s6.z+s7.z+s8.z)*(1.f/9.f);
            r.w = (s0.w+s1.w+s2.w+s3.w+s4.w+s5.w+s6.w+s7.w+s8.w)*(1.f/9.f);
            *(float4*)(co + o) = r;
        }
    }
    __syncthreads();
}

// K4: combine (gs precomputed) + pool2 + y-smooth
__global__ void comb_pool_smy_kernel(const float* __restrict__ gs,
                                     const float* __restrict__ pdd,
                                     const float* __restrict__ alpha,
                                     float* __restrict__ out) {
    extern __shared__ float sm[];
    float* colT = sm;
    float* MT   = sm + 225*CTC;
    int b = blockIdx.x, t = threadIdx.x;
    int k = b / NROWS, rc = b - k*NROWS;
    int iz = rc / 29, ix = rc - iz*29;
    size_t kb = (size_t)k*NP;
    size_t base = (kb + (size_t)iz*GS2 + ix) * 225;
    float a2 = alpha[2], a3 = alpha[3], a4 = alpha[4];

    const float* gg = gs  + base + t;
    const float* pd = pdd + base + t;

    float r[29];
#pragma unroll
    for (int c = 0; c < 2; c++) {
        const int y0c = c*16;
        const int nv = (c == 0) ? 16 : 13;
        if (t < 225) {
#pragma unroll
            for (int yy = 0; yy < nv; yy++) {
                size_t o = (size_t)(y0c+yy)*YSTRIDE;
                colT[t*CTC + yy] = a4 + a2*pd[o] + a3*gg[o];
            }
        }
        __syncthreads();
        pool_chunk(colT, MT, t);
        if (t < 225) {
#pragma unroll
            for (int yy = 0; yy < nv; yy++) r[y0c+yy] = colT[t*CTC + yy];
        }
        __syncthreads();
    }
    if (t < 225) {
        float* g = out + base + t;
#pragma unroll
        for (int y = 0; y < 29; y++) {
            int y0 = y-2 < 0 ? 0 : y-2;
            int y1 = y-1 < 0 ? 0 : y-1;
            int y3 = y+1 > 28 ? 28 : y+1;
            int y4c = y+2 > 28 ? 28 : y+2;
            g[(size_t)y*YSTRIDE] = W5_0*(r[y0]+r[y4c]) + W5_1*(r[y1]+r[y3]) + W5_2*r[y];
        }
    }
}

// K6: softmax + pred_xyz, batched 3-k reductions
__global__ void softmax_kernel(const float* __restrict__ cavg_p,
                               const float* __restrict__ shift2d,
                               const float* __restrict__ alpha,
                               float* __restrict__ out_soft,
                               float* __restrict__ out_cavg,
                               float* __restrict__ out_pred) {
    __shared__ float sred[24];
    __shared__ float ssh[PP*9];
    __shared__ float ssoft[PK];
    __shared__ float scav[PK];
    int n = blockIdx.x, tid = threadIdx.x;
    int lane = tid & 31, wid = tid >> 5;
    for (int idx = tid; idx < PP*9; idx += 256) ssh[idx] = shift2d[idx];
    float a5 = alpha[5];
    float cv0 = 0.f, cv1 = 0.f, cv2 = 0.f;
    bool act = (tid < 225);
    if (act) {
        cv0 = cavg_p[((size_t)0*NP + n)*225 + tid];
        cv1 = cavg_p[((size_t)1*NP + n)*225 + tid];
        cv2 = cavg_p[((size_t)2*NP + n)*225 + tid];
    }
    float t0 = act ? -a5*cv0 : -CUDART_INF_F;
    float t1 = act ? -a5*cv1 : -CUDART_INF_F;
    float t2 = act ? -a5*cv2 : -CUDART_INF_F;

    float m0 = t0, m1 = t1, m2 = t2;
#pragma unroll
    for (int o = 16; o; o >>= 1) {
        m0 = fmaxf(m0, __shfl_xor_sync(0xffffffffu, m0, o));
        m1 = fmaxf(m1, __shfl_xor_sync(0xffffffffu, m1, o));
        m2 = fmaxf(m2, __shfl_xor_sync(0xffffffffu, m2, o));
    }
    if (lane == 0) { sred[wid*3+0] = m0; sred[wid*3+1] = m1; sred[wid*3+2] = m2; }
    __syncthreads();
    float M0 = sred[0], M1 = sred[1], M2 = sred[2];
#pragma unroll
    for (int w = 1; w < 8; w++) {
        M0 = fmaxf(M0, sred[w*3+0]);
        M1 = fmaxf(M1, sred[w*3+1]);
        M2 = fmaxf(M2, sred[w*3+2]);
    }
    __syncthreads();

    float e0 = act ? expf(t0 - M0) : 0.f;
    float e1 = act ? expf(t1 - M1) : 0.f;
    float e2 = act ? expf(t2 - M2) : 0.f;

    float s0 = e0, s1 = e1, s2 = e2;
#pragma unroll
    for (int o = 16; o; o >>= 1) {
        s0 += __shfl_xor_sync(0xffffffffu, s0, o);
        s1 += __shfl_xor_sync(0xffffffffu, s1, o);
        s2 += __shfl_xor_sync(0xffffffffu, s2, o);
    }
    if (lane == 0) { sred[wid*3+0] = s0; sred[wid*3+1] = s1; sred[wid*3+2] = s2; }
    __syncthreads();
    float S0 = 0.f, S1 = 0.f, S2 = 0.f;
#pragma unroll
    for (int w = 0; w < 8; w++) {
        S0 += sred[w*3+0]; S1 += sred[w*3+1]; S2 += sred[w*3+2];
    }
    __syncthreads();

    float acc[3] = {0.f, 0.f, 0.f};
    if (act) {
        float soft0 = e0 / S0, soft1 = e1 / S1, soft2 = e2 / S2;
        ssoft[tid*3+0] = soft0; scav[tid*3+0] = cv0;
        ssoft[tid*3+1] = soft1; scav[tid*3+1] = cv1;
        ssoft[tid*3+2] = soft2; scav[tid*3+2] = cv2;
        const float* sh = &ssh[tid*9];
#pragma unroll
        for (int d = 0; d < 3; d++)
            acc[d] = soft0*sh[0*3+d] + soft1*sh[1*3+d] + soft2*sh[2*3+d];
    }
#pragma unroll
    for (int o = 16; o; o >>= 1) {
        acc[0] += __shfl_xor_sync(0xffffffffu, acc[0], o);
        acc[1] += __shfl_xor_sync(0xffffffffu, acc[1], o);
        acc[2] += __shfl_xor_sync(0xffffffffu, acc[2], o);
    }
    if (lane == 0) { sred[wid*3+0] = acc[0]; sred[wid*3+1] = acc[1]; sred[wid*3+2] = acc[2]; }
    __syncthreads();
    if (tid == 0) {
        float p0 = 0.f, p1 = 0.f, p2 = 0.f;
#pragma unroll
        for (int w = 0; w < 8; w++) {
            p0 += sred[w*3+0]; p1 += sred[w*3+1]; p2 += sred[w*3+2];
        }
        out_pred[n*3+0] = 0.5f*p0;
        out_pred[n*3+1] = 0.5f*p1;
        out_pred[n*3+2] = 0.5f*p2;
    }
    __syncthreads();
    float* so = out_soft + (size_t)n*PK;
    float* co = out_cavg + (size_t)n*PK;
    for (int idx = tid; idx < PK; idx += 256) {
        so[idx] = ssoft[idx];
        co[idx] = scav[idx];
    }
}

extern "C" void kernel_launch(void* const* d_in, const int* in_sizes, int n_in,
                              void* d_out, int out_size) {
    (void)in_sizes; (void)n_in; (void)out_size;
    const float* feat00   = (const float*)d_in[0];
    const float* feat50   = (const float*)d_in[1];
    const float* shift2d  = (const float*)d_in[4];
    const float* alpha    = (const float*)d_in[5];

    float* out = (float*)d_out;
    float* out_soft = out;
    float* out_pred = out + (size_t)NP * PK;
    float* out_cavg = out_pred + (size_t)NP * 3;

    float *p_pdd, *p_b1, *p_b2;
    cudaGetSymbolAddress((void**)&p_pdd, g_pdd);
    cudaGetSymbolAddress((void**)&p_b1,  g_b1);
    cudaGetSymbolAddress((void**)&p_b2,  g_b2);

    cudaFuncSetAttribute(pdd_slab_kernel,
                         cudaFuncAttributeMaxDynamicSharedMemorySize, SMEM_PDD);
    cudaFuncSetAttribute(comb_pool_smy_kernel,
                         cudaFuncAttributeMaxDynamicSharedMemorySize, SMEM_POOL);

    transpose_kernel<<<(VV*VV*VV + 255)/256, 256>>>(feat00, feat50);
    // pdd + pool1 -> b1 (and raw pdd)
    pdd_slab_kernel<<<dim3(NROWS, 3), PDD_THREADS, SMEM_PDD>>>(alpha);
    // grid_smooth of pooled: y then z (each element read once)
    smooth_y_kernel<<<3*NROWS, 256>>>(p_b1, p_b2);
    smooth_z_kernel<<<3*NROWS, 256>>>(p_b2, p_b1);
    // combine + pool2 + y-smooth -> b2
    comb_pool_smy_kernel<<<3*NROWS, 320, SMEM_POOL>>>(p_b1, p_pdd, alpha, p_b2);
    // final z-smooth -> b1 (planar cost_avg)
    smooth_z_kernel<<<3*NROWS, 256>>>(p_b2, p_b1);
    softmax_kernel<<<NP, 256>>>(p_b1, shift2d, alpha, out_soft, out_cavg, out_pred);
}

// round 16
// speedup vs baseline: 1.0158x; 1.0158x over previous
#include <cuda_runtime.h>
#include <math_constants.h>

#define GS 29
#define GS2 841
#define NP 24389
#define DW 15
#define PP 225
#define PK 675
#define VV 64
#define CC 8
#define NROWS 841
#define NSAMP (29*PP)
#define YSTRIDE (29*225)
#define ZSTRIDE (GS2*225)
#define CTC 20

// ---------------- device scratch ----------------
__device__ float g_f00 [VV*VV*VV*CC];
__device__ float g_f50x[VV*VV*VV*CC];
__device__ float g_f50y[VV*VV*VV*CC];
__device__ float g_pdd[3*(size_t)NP*PP];
__device__ float g_b1 [3*(size_t)NP*PP];
__device__ float g_b2 [3*(size_t)NP*PP];

__device__ __forceinline__ float A29(int i) { return (2.f*i + 1.f)/29.f - 1.f; }
__device__ __forceinline__ float to_pix(float t) { return 0.5f*((t + 1.f)*64.f - 1.f); }
__device__ __forceinline__ float SD(int t)  { return 0.4f*((2.f*t + 1.f)/15.f - 1.f); }

#define W5_0 (1.f/9.f)
#define W5_1 (2.f/9.f)
#define W5_2 (3.f/9.f)

// ---------------- K1: channels-last transpose ----------------
__global__ void transpose_kernel(const float* __restrict__ f00,
                                 const float* __restrict__ f50) {
    int idx = blockIdx.x * blockDim.x + threadIdx.x;
    if (idx >= VV*VV*VV) return;
    int x = idx & 63, y = (idx >> 6) & 63, z = idx >> 12;
    int yf = ((z*VV + x)*VV + y) * CC;
    int xf = idx * CC;
#pragma unroll
    for (int c = 0; c < CC; c++) {
        float v0 = f00[((c*VV + z)*VV + y)*VV + x];
        float v5 = f50[((c*VV + z)*VV + y)*VV + x];
        g_f00 [xf + c] = v0;
        g_f50x[xf + c] = v5;
        g_f50y[yf + c] = v5;
    }
}

// clamped trilerp of 8 channels, x-fast channels-last, pixel coords
__device__ __forceinline__ void trilerp8(const float* __restrict__ vol,
                                         float u, float v, float w,
                                         float* out8) {
    float uf = floorf(u), vf = floorf(v), wf = floorf(w);
    float fu = u - uf, fv = v - vf, fw = w - wf;
    int u0 = (int)uf, v0 = (int)vf, w0 = (int)wf;
    int uc[2] = { min(max(u0,0),63), min(max(u0+1,0),63) };
    int vc[2] = { min(max(v0,0),63), min(max(v0+1,0),63) };
    int wc[2] = { min(max(w0,0),63), min(max(w0+1,0),63) };
    float wu[2] = {1.f-fu, fu}, wv[2] = {1.f-fv, fv}, ww[2] = {1.f-fw, fw};
#pragma unroll
    for (int c = 0; c < 8; c++) out8[c] = 0.f;
#pragma unroll
    for (int a = 0; a < 2; a++)
#pragma unroll
      for (int b = 0; b < 2; b++) {
        int base = (wc[a]*64 + vc[b]) * 64;
        float wab = ww[a]*wv[b];
#pragma unroll
        for (int d = 0; d < 2; d++) {
            const float4* p = (const float4*)(vol + (size_t)(base + uc[d]) * 8);
            float wt = wab * wu[d];
            float4 x0 = p[0], x1 = p[1];
            out8[0]+=wt*x0.x; out8[1]+=wt*x0.y; out8[2]+=wt*x0.z; out8[3]+=wt*x0.w;
            out8[4]+=wt*x1.x; out8[5]+=wt*x1.y; out8[6]+=wt*x1.z; out8[7]+=wt*x1.w;
        }
      }
}

__device__ __forceinline__ float4 min4(float4 a, float4 b) {
    return make_float4(fminf(a.x,b.x), fminf(a.y,b.y), fminf(a.z,b.z), fminf(a.w,b.w));
}

// ---------------- separable pooling (used inside pdd only) ----------------
#define POOL_BUF_FLOATS ((225+255+289)*CTC)
#define SMEM_POOLBIG (POOL_BUF_FLOATS*4)

__device__ __forceinline__ void pool_sep_min(float* colT, float* R, float* M, int t) {
    if (t < 255) {
        int r = t / 17, j = t - r*17;
        int cb0 = min(max(j-2, 0), 14), cb1 = min(max(j-1, 0), 14), cb2 = min(j, 14);
        int q0 = (r*15+cb0)*CTC, q1 = (r*15+cb1)*CTC, q2 = (r*15+cb2)*CTC;
        float* ro = R + t*CTC;
#pragma unroll
        for (int y4 = 0; y4 < 4; y4++) {
            int o = y4*4;
            *(float4*)(ro+o) = min4(min4(*(float4*)(colT+q0+o), *(float4*)(colT+q1+o)),
                                    *(float4*)(colT+q2+o));
        }
    }
    __syncthreads();
    if (t < 289) {
        int i = t / 17, j = t - i*17;
        int ra0 = (min(max(i-2,0),14)*17 + j)*CTC;
        int ra1 = (min(max(i-1,0),14)*17 + j)*CTC;
        int ra2 = (min(i,14)*17 + j)*CTC;
        float* mo = M + t*CTC;
#pragma unroll
        for (int y4 = 0; y4 < 4; y4++) {
            int o = y4*4;
            *(float4*)(mo+o) = min4(min4(*(float4*)(R+ra0+o), *(float4*)(R+ra1+o)),
                                    *(float4*)(R+ra2+o));
        }
    }
    __syncthreads();
    if (t < 255) {
        int x = t / 15, y = t - x*15;
        int m0 = (x*17+y)*CTC;
        float* ro = R + t*CTC;
#pragma unroll
        for (int y4 = 0; y4 < 4; y4++) {
            int o = y4*4;
            float4 a = *(float4*)(M+m0+o), b = *(float4*)(M+m0+CTC+o), c = *(float4*)(M+m0+2*CTC+o);
            *(float4*)(ro+o) = make_float4(a.x+b.x+c.x, a.y+b.y+c.y, a.z+b.z+c.z, a.w+b.w+c.w);
        }
    }
    __syncthreads();
}

// ---------------- K2: pdd + fused pool1, separable v-then-u interpolation ----------------
#define SLAB_F4 (64*27)
#define VS_F4   1024
#define SMEM_PDD_RAW ((2*SLAB_F4 + 2*VS_F4)*16 + (232+15+29)*4)
#define SMEM_PDD ((SMEM_PDD_RAW > SMEM_POOLBIG) ? SMEM_PDD_RAW : SMEM_POOLBIG)
#define PDD_THREADS 512
#define CPT 13

__global__ void __launch_bounds__(PDD_THREADS, 2)
pdd_slab_kernel(const float* __restrict__ alpha) {
    extern __shared__ char smraw[];
    float4* sLo  = (float4*)smraw;
    float4* sHi  = sLo + SLAB_F4;
    float4* VSa  = sHi + SLAB_F4;
    float4* VSb  = VSa + VS_F4;
    float*  fixf = (float*)(VSb + VS_F4);
    float*  sdisp = fixf + 232;
    float*  a29s  = sdisp + 15;
    float*  colT = (float*)smraw;
    float*  Rbuf = colT + 225*CTC;
    float*  Mbuf = Rbuf + 255*CTC;

    const int r   = blockIdx.x;
    const int k   = blockIdx.y;
    const int tid = threadIdx.x;

    if (tid < 29) a29s[tid] = A29(tid);
    if (tid >= 32 && tid < 47) sdisp[tid-32] = SD(tid-32);

    const int i1 = r / 29, i2 = r - (r/29)*29;
    float aV, cW;
    if (k == 0)      { aV = A29(i2); cW = to_pix(A29(i1)); }
    else             { aV = A29(i1); cW = to_pix(A29(i2)); }
    const float sd0  = SD(0);
    const float vmin = 0.5f*((aV + sd0 + 1.f)*64.f - 1.f);
    const int vbase  = (int)floorf(vmin);
    const float wfl = floorf(cW);
    const float fw  = cW - wfl;
    const int w0 = min(max((int)wfl,   0), 63);
    const int w1 = min(max((int)wfl+1, 0), 63);
    const float vbias = fmaf(aV, 32.f, 31.5f);

    // ---- slab fill (pre-interp fixed axis) ----
    if (k == 0) {
        for (int pos = tid; pos < 64*26; pos += PDD_THREADS) {
            int u = pos & 63, vi = pos >> 6;
            int y = min(max(vbase + vi, 0), 63);
            const float4* p0 = (const float4*)&g_f50x[(size_t)((w0*64 + y)*64 + u)*8];
            const float4* p1 = (const float4*)&g_f50x[(size_t)((w1*64 + y)*64 + u)*8];
            float4 a0=p0[0], b0=p0[1], a1=p1[0], b1=p1[1];
            float4 lo, hi;
            lo.x=a0.x+fw*(a1.x-a0.x); lo.y=a0.y+fw*(a1.y-a0.y); lo.z=a0.z+fw*(a1.z-a0.z); lo.w=a0.w+fw*(a1.w-a0.w);
            hi.x=b0.x+fw*(b1.x-b0.x); hi.y=b0.y+fw*(b1.y-b0.y); hi.z=b0.z+fw*(b1.z-b0.z); hi.w=b0.w+fw*(b1.w-b0.w);
            sLo[u*27+vi]=lo; sHi[u*27+vi]=hi;
        }
    } else if (k == 1) {
        for (int pos = tid; pos < 64*26; pos += PDD_THREADS) {
            int u = pos & 63, vi = pos >> 6;
            int z = min(max(vbase + vi, 0), 63);
            const float4* p0 = (const float4*)&g_f50x[(size_t)((z*64 + w0)*64 + u)*8];
            const float4* p1 = (const float4*)&g_f50x[(size_t)((z*64 + w1)*64 + u)*8];
            float4 a0=p0[0], b0=p0[1], a1=p1[0], b1=p1[1];
            float4 lo, hi;
            lo.x=a0.x+fw*(a1.x-a0.x); lo.y=a0.y+fw*(a1.y-a0.y); lo.z=a0.z+fw*(a1.z-a0.z); lo.w=a0.w+fw*(a1.w-a0.w);
            hi.x=b0.x+fw*(b1.x-b0.x); hi.y=b0.y+fw*(b1.y-b0.y); hi.z=b0.z+fw*(b1.z-b0.z); hi.w=b0.w+fw*(b1.w-b0.w);
            sLo[u*27+vi]=lo; sHi[u*27+vi]=hi;
        }
    } else {
        for (int pos = tid; pos < 64*26; pos += PDD_THREADS) {
            int vi = pos % 26, u = pos / 26;
            int y = min(max(vbase + vi, 0), 63);
            const float4* p0 = (const float4*)&g_f50y[(size_t)((u*64 + w0)*64 + y)*8];
            const float4* p1 = (const float4*)&g_f50y[(size_t)((u*64 + w1)*64 + y)*8];
            float4 a0=p0[0], b0=p0[1], a1=p1[0], b1=p1[1];
            float4 lo, hi;
            lo.x=a0.x+fw*(a1.x-a0.x); lo.y=a0.y+fw*(a1.y-a0.y); lo.z=a0.z+fw*(a1.z-a0.z); lo.w=a0.w+fw*(a1.w-a0.w);
            hi.x=b0.x+fw*(b1.x-b0.x); hi.y=b0.y+fw*(b1.y-b0.y); hi.z=b0.z+fw*(b1.z-b0.z); hi.w=b0.w+fw*(b1.w-b0.w);
            sLo[u*27+vi]=lo; sHi[u*27+vi]=hi;
        }
    }

    if (tid < 29) {
        float px, py, pz;
        if (k < 2) { px = to_pix(A29(tid)); py = to_pix(A29(i2)); pz = to_pix(A29(i1)); }
        else       { px = to_pix(A29(i2)); py = to_pix(A29(i1)); pz = to_pix(A29(tid)); }
        trilerp8(g_f00, px, py, pz, &fixf[tid*8]);
    }
    __syncthreads();

    // ---- stage B: v-interp 15 distinct v values ----
    for (int t = tid; t < 15*64; t += PDD_THREADS) {
        int u, vi;
        if (k == 2) { u = t / 15; vi = t - u*15; }
        else        { vi = t >> 6; u = t & 63; }
        float v = fmaf(SD(vi), 32.f, vbias);
        float vf = floorf(v);
        float fv = v - vf;
        int iv = (int)vf - vbase;
        int v0 = min(max(iv,   0), 25);
        int v1 = min(max(iv+1, 0), 25);
        float4 l0 = sLo[u*27+v0], l1 = sLo[u*27+v1];
        float4 h0 = sHi[u*27+v0], h1 = sHi[u*27+v1];
        float4 lo, hi;
        lo.x=l0.x+fv*(l1.x-l0.x); lo.y=l0.y+fv*(l1.y-l0.y); lo.z=l0.z+fv*(l1.z-l0.z); lo.w=l0.w+fv*(l1.w-l0.w);
        hi.x=h0.x+fv*(h1.x-h0.x); hi.y=h0.y+fv*(h1.y-h0.y); hi.z=h0.z+fv*(h1.z-h0.z); hi.w=h0.w+fv*(h1.w-h0.w);
        int idx = (k == 2) ? (u*16 + vi) : (vi*64 + u);
        VSa[idx] = lo; VSb[idx] = hi;
    }
    __syncthreads();

    // ---- sample loop: 1-D u-lerp of VS ----
    const float a0c = alpha[0], a1c = alpha[1];
    float creg[CPT];
#pragma unroll
    for (int i = 0; i < CPT; i++) {
        int s = tid + i*PDD_THREADS;
        if (s < NSAMP) {
            int na = s / 225;
            int p  = s - na*225;
            int pi = p / 15, pj = p - pi*15;
            int ui = (k == 2) ? pi : pj;
            int vi = (k == 2) ? pj : pi;
            float u = fmaf(a29s[na] + sdisp[ui], 32.f, 31.5f);
            float uf = floorf(u);
            float fu = u - uf;
            int iu = (int)uf;
            int u0 = min(max(iu,   0), 63);
            int u1 = min(max(iu+1, 0), 63);
            int b0 = (k == 2) ? (u0*16 + vi) : (vi*64 + u0);
            int b1 = (k == 2) ? (u1*16 + vi) : (vi*64 + u1);
            float4 a0 = VSa[b0], a1 = VSa[b1];
            float4 h0 = VSb[b0], h1 = VSb[b1];
            const float4 fA = *(const float4*)&fixf[na*8];
            const float4 fB = *(const float4*)&fixf[na*8 + 4];
            float d, ssd = 0.f;
            d = fA.x - (a0.x + fu*(a1.x-a0.x)); ssd += d*d;
            d = fA.y - (a0.y + fu*(a1.y-a0.y)); ssd += d*d;
            d = fA.z - (a0.z + fu*(a1.z-a0.z)); ssd += d*d;
            d = fA.w - (a0.w + fu*(a1.w-a0.w)); ssd += d*d;
            d = fB.x - (h0.x + fu*(h1.x-h0.x)); ssd += d*d;
            d = fB.y - (h0.y + fu*(h1.y-h0.y)); ssd += d*d;
            d = fB.z - (h0.z + fu*(h1.z-h0.z)); ssd += d*d;
            d = fB.w - (h0.w + fu*(h1.w-h0.w)); ssd += d*d;
            float cval = a1c + a0c*ssd;
            creg[i] = cval;
            int n = (k < 2) ? (r*29 + na) : (na*841 + r);
            g_pdd[((size_t)k*NP + n)*225 + p] = cval;
        }
    }
    __syncthreads();

    const size_t obase = (size_t)k*NP*225 + ((k < 2) ? (size_t)r*29*225 : (size_t)r*225);
    const size_t nstep = (k < 2) ? (size_t)225 : (size_t)841*225;

#pragma unroll
    for (int cidx = 0; cidx < 2; cidx++) {
        const int na0 = cidx*16;
        const int nv  = cidx ? 13 : 16;
#pragma unroll
        for (int i = 0; i < CPT; i++) {
            int s = tid + i*PDD_THREADS;
            if (s < NSAMP) {
                int na = s / 225;
                int p  = s - na*225;
                int d = na - na0;
                if ((unsigned)d < (unsigned)nv) colT[p*CTC + d] = creg[i];
            }
        }
        __syncthreads();
        pool_sep_min(colT, Rbuf, Mbuf, tid);
        if (tid < 225) {
            int s0 = tid*CTC;
#pragma unroll
            for (int y4 = 0; y4 < 4; y4++) {
                int o = y4*4;
                float4 v0 = *(float4*)(Rbuf+s0+o);
                float4 v1 = *(float4*)(Rbuf+s0+15*CTC+o);
                float4 v2 = *(float4*)(Rbuf+s0+30*CTC+o);
                float rr[4] = {(v0.x+v1.x+v2.x)*(1.f/9.f), (v0.y+v1.y+v2.y)*(1.f/9.f),
                               (v0.z+v1.z+v2.z)*(1.f/9.f), (v0.w+v1.w+v2.w)*(1.f/9.f)};
#pragma unroll
                for (int l = 0; l < 4; l++) {
                    int d = y4*4 + l;
                    if (d < nv)
                        g_b1[obase + (size_t)(na0+d)*nstep + tid] = rr[l];
                }
            }
        }
        __syncthreads();
    }
}

// ---------------- K3: smooth_y register kernel ----------------
__global__ void smooth_y_kernel(const float* __restrict__ in, float* __restrict__ out) {
    int b = blockIdx.x, t = threadIdx.x;
    if (t >= 225) return;
    int k = b / NROWS, rc = b - k*NROWS;
    int iz = rc / 29, ix = rc - iz*29;
    size_t base = ((size_t)k*NP + (size_t)iz*GS2 + ix) * 225;
    float r[29];
    const float* g = in + base + t;
#pragma unroll
    for (int y = 0; y < 29; y++) r[y] = g[(size_t)y*YSTRIDE];
    float* go = out + base + t;
#pragma unroll
    for (int y = 0; y < 29; y++) {
        int y0 = y-2 < 0 ? 0 : y-2;
        int y1 = y-1 < 0 ? 0 : y-1;
        int y3 = y+1 > 28 ? 28 : y+1;
        int y4 = y+2 > 28 ? 28 : y+2;
        go[(size_t)y*YSTRIDE] = W5_0*(r[y0]+r[y4]) + W5_1*(r[y1]+r[y3]) + W5_2*r[y];
    }
}

// ---------------- smooth_z register kernel (used twice) ----------------
__global__ void smooth_z_kernel(const float* __restrict__ in, float* __restrict__ out) {
    int b = blockIdx.x, t = threadIdx.x;
    if (t >= 225) return;
    int k = b / NROWS, rc = b - k*NROWS;
    int iy = rc / 29, ix = rc - iy*29;
    size_t base = ((size_t)k*NP + (size_t)iy*GS + ix) * 225;
    float r[29];
    const float* g = in + base + t;
#pragma unroll
    for (int z = 0; z < 29; z++) r[z] = g[(size_t)z*ZSTRIDE];
    float* go = out + base + t;
#pragma unroll
    for (int z = 0; z < 29; z++) {
        int z0 = z-2 < 0 ? 0 : z-2;
        int z1 = z-1 < 0 ? 0 : z-1;
        int z3 = z+1 > 28 ? 28 : z+1;
        int z4 = z+2 > 28 ? 28 : z+2;
        go[(size_t)z*ZSTRIDE] = W5_0*(r[z0]+r[z4]) + W5_1*(r[z1]+r[z3]) + W5_2*r[z];
    }
}

// ---------------- round-6 9-tap pool chunk ----------------
#define SMEM_POOL ((225*CTC + 289*CTC)*4)

__device__ __forceinline__ void pool_chunk(float* colT, float* MT, int t) {
    if (t < 289) {
        int i = t / 17, j = t - i*17;
        int ra0 = min(max(i-2, 0), 14)*15, ra1 = min(max(i-1, 0), 14)*15, ra2 = min(i, 14)*15;
        int cb0 = min(max(j-2, 0), 14),    cb1 = min(max(j-1, 0), 14),    cb2 = min(j, 14);
        int p0 = (ra0+cb0)*CTC, p1 = (ra0+cb1)*CTC, p2 = (ra0+cb2)*CTC;
        int p3 = (ra1+cb0)*CTC, p4 = (ra1+cb1)*CTC, p5 = (ra1+cb2)*CTC;
        int p6 = (ra2+cb0)*CTC, p7 = (ra2+cb1)*CTC, p8 = (ra2+cb2)*CTC;
        float* mo = MT + t*CTC;
#pragma unroll
        for (int y4 = 0; y4 < 4; y4++) {
            int o = y4*4;
            float4 m = min4(*(float4*)(colT+p0+o), *(float4*)(colT+p1+o));
            m = min4(m, *(float4*)(colT+p2+o));
            m = min4(m, min4(*(float4*)(colT+p3+o), *(float4*)(colT+p4+o)));
            m = min4(m, *(float4*)(colT+p5+o));
            m = min4(m, min4(*(float4*)(colT+p6+o), *(float4*)(colT+p7+o)));
            m = min4(m, *(float4*)(colT+p8+o));
            *(float4*)(mo + o) = m;
        }
    }
    __syncthreads();
    if (t < 225) {
        int i = t / 15, j = t - i*15;
        int b0 = (i*17 + j)*CTC;
        float* co = colT + t*CTC;
#pragma unroll
        for (int y4 = 0; y4 < 4; y4++) {
            int o = y4*4;
            float4 s0 = *(float4*)(MT+b0+o);
            float4 s1 = *(float4*)(MT+b0+CTC+o);
            float4 s2 = *(float4*)(MT+b0+2*CTC+o);
            float4 s3 = *(float4*)(MT+b0+17*CTC+o);
            float4 s4 = *(float4*)(MT+b0+18*CTC+o);
            float4 s5 = *(float4*)(MT+b0+19*CTC+o);
            float4 s6 = *(float4*)(MT+b0+34*CTC+o);
            float4 s7 = *(float4*)(MT+b0+35*CTC+o);
            float4 s8 = *(float4*)(MT+b0+36*CTC+o);
            float4 r;
            r.x = (s0.x+s1.x+s2.x+s3.x+s4.x+s5.x+s6.x+s7.x+s8.x)*(1.f/9.f);
            r.y = (s0.y+s1.y+s2.y+s3.y+s4.y+s5.y+s6.y+s7.y+s8.y)*(1.f/9.f);
            r.z = (s0.z+s1.z+s2.z+s3.z+s4.z+s5.z+s6.z+s7.z+s8.z)*(1.f/9.f);
            r.w = (s0.w+s1.w+s2.w+s3.w+s4.w+s5.w+s6.w+s7.w+s8.w)*(1.f/9.f);
            *(float4*)(co + o) = r;
        }
    }
    __syncthreads();
}

// K4: combine (gs precomputed) + pool2 + y-smooth — occupancy 4 blocks/SM
__global__ void __launch_bounds__(320, 4)
comb_pool_smy_kernel(const float* __restrict__ gs,
                     const float* __restrict__ pdd,
                     const float* __restrict__ alpha,
                     float* __restrict__ out) {
    extern __shared__ float sm[];
    float* colT = sm;
    float* MT   = sm + 225*CTC;
    int b = blockIdx.x, t = threadIdx.x;
    int k = b / NROWS, rc = b - k*NROWS;
    int iz = rc / 29, ix = rc - iz*29;
    size_t kb = (size_t)k*NP;
    size_t base = (kb + (size_t)iz*GS2 + ix) * 225;
    float a2 = alpha[2], a3 = alpha[3], a4 = alpha[4];

    const float* gg = gs  + base + t;
    const float* pd = pdd + base + t;

    float r[29];
#pragma unroll
    for (int c = 0; c < 2; c++) {
        const int y0c = c*16;
        const int nv = (c == 0) ? 16 : 13;
        if (t < 225) {
#pragma unroll
            for (int yy = 0; yy < nv; yy++) {
                size_t o = (size_t)(y0c+yy)*YSTRIDE;
                colT[t*CTC + yy] = a4 + a2*pd[o] + a3*gg[o];
            }
        }
        __syncthreads();
        pool_chunk(colT, MT, t);
        if (t < 225) {
#pragma unroll
            for (int yy = 0; yy < nv; yy++) r[y0c+yy] = colT[t*CTC + yy];
        }
        __syncthreads();
    }
    if (t < 225) {
        float* g = out + base + t;
#pragma unroll
        for (int y = 0; y < 29; y++) {
            int y0 = y-2 < 0 ? 0 : y-2;
            int y1 = y-1 < 0 ? 0 : y-1;
            int y3 = y+1 > 28 ? 28 : y+1;
            int y4c = y+2 > 28 ? 28 : y+2;
            g[(size_t)y*YSTRIDE] = W5_0*(r[y0]+r[y4c]) + W5_1*(r[y1]+r[y3]) + W5_2*r[y];
        }
    }
}

// K6: softmax + pred_xyz, batched 3-k reductions
__global__ void softmax_kernel(const float* __restrict__ cavg_p,
                               const float* __restrict__ shift2d,
                               const float* __restrict__ alpha,
                               float* __restrict__ out_soft,
                               float* __restrict__ out_cavg,
                               float* __restrict__ out_pred) {
    __shared__ float sred[24];
    __shared__ float ssh[PP*9];
    __shared__ float ssoft[PK];
    __shared__ float scav[PK];
    int n = blockIdx.x, tid = threadIdx.x;
    int lane = tid & 31, wid = tid >> 5;
    for (int idx = tid; idx < PP*9; idx += 256) ssh[idx] = shift2d[idx];
    float a5 = alpha[5];
    float cv0 = 0.f, cv1 = 0.f, cv2 = 0.f;
    bool act = (tid < 225);
    if (act) {
        cv0 = cavg_p[((size_t)0*NP + n)*225 + tid];
        cv1 = cavg_p[((size_t)1*NP + n)*225 + tid];
        cv2 = cavg_p[((size_t)2*NP + n)*225 + tid];
    }
    float t0 = act ? -a5*cv0 : -CUDART_INF_F;
    float t1 = act ? -a5*cv1 : -CUDART_INF_F;
    float t2 = act ? -a5*cv2 : -CUDART_INF_F;

    float m0 = t0, m1 = t1, m2 = t2;
#pragma unroll
    for (int o = 16; o; o >>= 1) {
        m0 = fmaxf(m0, __shfl_xor_sync(0xffffffffu, m0, o));
        m1 = fmaxf(m1, __shfl_xor_sync(0xffffffffu, m1, o));
        m2 = fmaxf(m2, __shfl_xor_sync(0xffffffffu, m2, o));
    }
    if (lane == 0) { sred[wid*3+0] = m0; sred[wid*3+1] = m1; sred[wid*3+2] = m2; }
    __syncthreads();
    float M0 = sred[0], M1 = sred[1], M2 = sred[2];
#pragma unroll
    for (int w = 1; w < 8; w++) {
        M0 = fmaxf(M0, sred[w*3+0]);
        M1 = fmaxf(M1, sred[w*3+1]);
        M2 = fmaxf(M2, sred[w*3+2]);
    }
    __syncthreads();

    float e0 = act ? expf(t0 - M0) : 0.f;
    float e1 = act ? expf(t1 - M1) : 0.f;
    float e2 = act ? expf(t2 - M2) : 0.f;

    float s0 = e0, s1 = e1, s2 = e2;
#pragma unroll
    for (int o = 16; o; o >>= 1) {
        s0 += __shfl_xor_sync(0xffffffffu, s0, o);
        s1 += __shfl_xor_sync(0xffffffffu, s1, o);
        s2 += __shfl_xor_sync(0xffffffffu, s2, o);
    }
    if (lane == 0) { sred[wid*3+0] = s0; sred[wid*3+1] = s1; sred[wid*3+2] = s2; }
    __syncthreads();
    float S0 = 0.f, S1 = 0.f, S2 = 0.f;
#pragma unroll
    for (int w = 0; w < 8; w++) {
        S0 += sred[w*3+0]; S1 += sred[w*3+1]; S2 += sred[w*3+2];
    }
    __syncthreads();

    float acc[3] = {0.f, 0.f, 0.f};
    if (act) {
        float soft0 = e0 / S0, soft1 = e1 / S1, soft2 = e2 / S2;
        ssoft[tid*3+0] = soft0; scav[tid*3+0] = cv0;
        ssoft[tid*3+1] = soft1; scav[tid*3+1] = cv1;
        ssoft[tid*3+2] = soft2; scav[tid*3+2] = cv2;
        const float* sh = &ssh[tid*9];
#pragma unroll
        for (int d = 0; d < 3; d++)
            acc[d] = soft0*sh[0*3+d] + soft1*sh[1*3+d] + soft2*sh[2*3+d];
    }
#pragma unroll
    for (int o = 16; o; o >>= 1) {
        acc[0] += __shfl_xor_sync(0xffffffffu, acc[0], o);
        acc[1] += __shfl_xor_sync(0xffffffffu, acc[1], o);
        acc[2] += __shfl_xor_sync(0xffffffffu, acc[2], o);
    }
    if (lane == 0) { sred[wid*3+0] = acc[0]; sred[wid*3+1] = acc[1]; sred[wid*3+2] = acc[2]; }
    __syncthreads();
    if (tid == 0) {
        float p0 = 0.f, p1 = 0.f, p2 = 0.f;
#pragma unroll
        for (int w = 0; w < 8; w++) {
            p0 += sred[w*3+0]; p1 += sred[w*3+1]; p2 += sred[w*3+2];
        }
        out_pred[n*3+0] = 0.5f*p0;
        out_pred[n*3+1] = 0.5f*p1;
        out_pred[n*3+2] = 0.5f*p2;
    }
    __syncthreads();
    float* so = out_soft + (size_t)n*PK;
    float* co = out_cavg + (size_t)n*PK;
    for (int idx = tid; idx < PK; idx += 256) {
        so[idx] = ssoft[idx];
        co[idx] = scav[idx];
    }
}

extern "C" void kernel_launch(void* const* d_in, const int* in_sizes, int n_in,
                              void* d_out, int out_size) {
    (void)in_sizes; (void)n_in; (void)out_size;
    const float* feat00   = (const float*)d_in[0];
    const float* feat50   = (const float*)d_in[1];
    const float* shift2d  = (const float*)d_in[4];
    const float* alpha    = (const float*)d_in[5];

    float* out = (float*)d_out;
    float* out_soft = out;
    float* out_pred = out + (size_t)NP * PK;
    float* out_cavg = out_pred + (size_t)NP * 3;

    float *p_pdd, *p_b1, *p_b2;
    cudaGetSymbolAddress((void**)&p_pdd, g_pdd);
    cudaGetSymbolAddress((void**)&p_b1,  g_b1);
    cudaGetSymbolAddress((void**)&p_b2,  g_b2);

    cudaFuncSetAttribute(pdd_slab_kernel,
                         cudaFuncAttributeMaxDynamicSharedMemorySize, SMEM_PDD);
    cudaFuncSetAttribute(comb_pool_smy_kernel,
                         cudaFuncAttributeMaxDynamicSharedMemorySize, SMEM_POOL);

    transpose_kernel<<<(VV*VV*VV + 255)/256, 256>>>(feat00, feat50);
    pdd_slab_kernel<<<dim3(NROWS, 3), PDD_THREADS, SMEM_PDD>>>(alpha);
    smooth_y_kernel<<<3*NROWS, 256>>>(p_b1, p_b2);
    smooth_z_kernel<<<3*NROWS, 256>>>(p_b2, p_b1);
    comb_pool_smy_kernel<<<3*NROWS, 320, SMEM_POOL>>>(p_b1, p_pdd, alpha, p_b2);
    smooth_z_kernel<<<3*NROWS, 256>>>(p_b2, p_b1);
    softmax_kernel<<<NP, 256>>>(p_b1, shift2d, alpha, out_soft, out_cavg, out_pred);
}